// round 5
// baseline (speedup 1.0000x reference)
#include <cuda_runtime.h>
#include <cuda_fp16.h>
#include <cstdint>
#include <math.h>

// ---------------- problem constants ----------------
#define NN    50000
#define F0    128
#define H0    4
#define HC0   256
#define HC1   64
#define EMAX  900000

// ---------------- scratch ----------------
__device__ __half g_lin0h[(size_t)NN * HC0];   // gemm0 output, fp16
__device__ float  g_feat [(size_t)NN * HC0];   // relu(agg0 + b0) -> gemm1 input (fp32)
__device__ __half g_lin1h[(size_t)NN * HC1];   // gemm1 output, fp16
__device__ float  g_as0 [NN * H0];
__device__ float  g_ad0 [NN * H0];
__device__ float  g_as1 [NN];
__device__ float  g_ad1 [NN];
__device__ int    g_deg [NN];
__device__ int    g_row [NN + 1];
__device__ int    g_cur [NN];
__device__ int    g_srcl[EMAX];

__device__ __forceinline__ float leaky02(float v) { return v > 0.0f ? v : 0.2f * v; }

__device__ __forceinline__ void edge_sd(const int* __restrict__ ei, int e, int E, int& s, int& d) {
    if (e < E) { s = ei[e]; d = ei[E + e]; } else { s = e - E; d = e - E; }
}

// ---------------- CSR build ----------------
__global__ void k_zero_deg() {
    int i = blockIdx.x * blockDim.x + threadIdx.x;
    if (i < NN) g_deg[i] = 0;
}
__global__ void k_hist(const int* __restrict__ ei, int E, int Etot) {
    int e = blockIdx.x * blockDim.x + threadIdx.x;
    if (e >= Etot) return;
    int s, d; edge_sd(ei, e, E, s, d);
    atomicAdd(&g_deg[d], 1);
}
__global__ void k_scan() {
    __shared__ int ssum[1024];
    const int t  = threadIdx.x;
    const int CH = (NN + 1023) / 1024;
    int beg = t * CH;
    int end = min(beg + CH, NN);
    int s = 0;
    for (int j = beg; j < end; j++) s += g_deg[j];
    ssum[t] = s;
    __syncthreads();
    for (int o = 1; o < 1024; o <<= 1) {
        int v = (t >= o) ? ssum[t - o] : 0;
        __syncthreads();
        ssum[t] += v;
        __syncthreads();
    }
    int run = (t == 0) ? 0 : ssum[t - 1];
    for (int j = beg; j < end; j++) {
        int dv = g_deg[j];
        g_row[j] = run;
        g_cur[j] = run;
        run += dv;
    }
    if (t == 1023) g_row[NN] = run;
}
__global__ void k_scatter(const int* __restrict__ ei, int E, int Etot) {
    int e = blockIdx.x * blockDim.x + threadIdx.x;
    if (e >= Etot) return;
    int s, d; edge_sd(ei, e, E, s, d);
    int pos = atomicAdd(&g_cur[d], 1);
    g_srcl[pos] = s;
}

// ---------------- GEMM (fp32x2 FMA, fp32 accum) -> fp16 C + fused attention coefs ----------------
template<int BM, int BN, int BK, int TM, int TN>
__global__ void __launch_bounds__((BM/TM)*(BN/TN))
gemm_nt(const float* __restrict__ A, const float* __restrict__ B,
        __half* __restrict__ Ch, int M, int Nc, int K,
        const float* __restrict__ att_s, const float* __restrict__ att_d,
        float* __restrict__ as_out, float* __restrict__ ad_out)
{
    constexpr int THREADS = (BM/TM)*(BN/TN);
    constexpr int BMP = BM + 4;
    constexpr int BNP = BN + 4;
    __shared__ __align__(16) float As[BK][BMP];
    __shared__ __align__(16) float Bs[BK][BNP];

    const int tid = threadIdx.x;
    const int tx  = tid % (BN/TN);
    const int ty  = tid / (BN/TN);
    const int rowBase = blockIdx.x * BM;
    const int colBase = blockIdx.y * BN;

    unsigned long long acc2[TM][TN/2];
#pragma unroll
    for (int i = 0; i < TM; i++)
#pragma unroll
        for (int j = 0; j < TN/2; j++) acc2[i][j] = 0ull;

    for (int k0 = 0; k0 < K; k0 += BK) {
        constexpr int AF4 = BM * BK / 4;
#pragma unroll
        for (int i = 0; i < AF4 / THREADS; i++) {
            int f  = tid + i * THREADS;
            int r  = f / (BK/4);
            int c4 = f % (BK/4);
            float4 v = make_float4(0.f, 0.f, 0.f, 0.f);
            int gr = rowBase + r;
            if (gr < M) v = *(const float4*)(A + (size_t)gr * K + k0 + c4 * 4);
            As[c4*4+0][r] = v.x; As[c4*4+1][r] = v.y;
            As[c4*4+2][r] = v.z; As[c4*4+3][r] = v.w;
        }
        constexpr int BF4 = BN * BK / 4;
#pragma unroll
        for (int i = 0; i < BF4 / THREADS; i++) {
            int f  = tid + i * THREADS;
            int r  = f / (BK/4);
            int c4 = f % (BK/4);
            float4 v = *(const float4*)(B + (size_t)(colBase + r) * K + k0 + c4 * 4);
            Bs[c4*4+0][r] = v.x; Bs[c4*4+1][r] = v.y;
            Bs[c4*4+2][r] = v.z; Bs[c4*4+3][r] = v.w;
        }
        __syncthreads();

#pragma unroll
        for (int k = 0; k < BK; k++) {
            float a[TM];
            const float4* ap = (const float4*)&As[k][ty * TM];
            ((float4*)a)[0] = ap[0]; ((float4*)a)[1] = ap[1];
            unsigned long long b2[TN/2];
            const unsigned long long* bp = (const unsigned long long*)&Bs[k][tx * TN];
#pragma unroll
            for (int j = 0; j < TN/2; j++) b2[j] = bp[j];
#pragma unroll
            for (int i = 0; i < TM; i++) {
                unsigned long long a2;
                asm("mov.b64 %0, {%1, %1};" : "=l"(a2) : "f"(a[i]));
#pragma unroll
                for (int j = 0; j < TN/2; j++)
                    asm("fma.rn.f32x2 %0, %1, %2, %0;"
                        : "+l"(acc2[i][j]) : "l"(a2), "l"(b2[j]));
            }
        }
        __syncthreads();
    }

    // ---- store C as fp16 (8 halves = one uint4 per row fragment) ----
#pragma unroll
    for (int i = 0; i < TM; i++) {
        int gr = rowBase + ty * TM + i;
        if (gr < M) {
            const float* af = (const float*)acc2[i];
            union { uint4 u; __half2 h[4]; } pk;
#pragma unroll
            for (int j = 0; j < 4; j++)
                pk.h[j] = __floats2half2_rn(af[2*j], af[2*j+1]);
            *(uint4*)(Ch + (size_t)gr * Nc + colBase + tx * TN) = pk.u;
        }
    }

    // ---- fused attention coefficients (BN==64 == one head), fp32 exact ----
    {
        const int Hh   = Nc >> 6;
        const int head = colBase >> 6;
        float asv[TN], adv[TN];
#pragma unroll
        for (int j = 0; j < TN; j++) {
            asv[j] = att_s[colBase + tx * TN + j];
            adv[j] = att_d[colBase + tx * TN + j];
        }
#pragma unroll
        for (int i = 0; i < TM; i++) {
            const float* af = (const float*)acc2[i];
            float ps = 0.f, pd = 0.f;
#pragma unroll
            for (int j = 0; j < TN; j++) {
                ps = fmaf(af[j], asv[j], ps);
                pd = fmaf(af[j], adv[j], pd);
            }
#pragma unroll
            for (int o = 1; o < (BN/TN); o <<= 1) {
                ps += __shfl_xor_sync(0xffffffffu, ps, o);
                pd += __shfl_xor_sync(0xffffffffu, pd, o);
            }
            int gr = rowBase + ty * TM + i;
            if (tx == 0 && gr < M) {
                as_out[gr * Hh + head] = ps;
                ad_out[gr * Hh + head] = pd;
            }
        }
    }
}

// ---------------- aggregation layer 0: block(128) per dst, inline softmax weights ----------------
#define AGG_CH 128
__global__ void __launch_bounds__(128)
k_agg0(const float* __restrict__ b0)
{
    const int d   = blockIdx.x;
    const int tid = threadIdx.x;
    const int h   = tid >> 5;

    __shared__ int   s_sm [AGG_CH];
    __shared__ float ew_sm[AGG_CH * 4];

    const int beg = g_row[d];
    const int n   = g_row[d + 1] - beg;
    const float4 ad = *(const float4*)(g_ad0 + d * 4);

    float2 acc = make_float2(0.f, 0.f);
    float  den = 0.f;
    const __half2* lin = (const __half2*)g_lin0h;

    for (int c0 = 0; c0 < n; c0 += AGG_CH) {
        const int cn = min(AGG_CH, n - c0);
        __syncthreads();
        if (tid < cn) {
            int s = g_srcl[beg + c0 + tid];
            s_sm[tid] = s;
            float4 a = *(const float4*)(g_as0 + s * 4);
            float4 w;
            w.x = __expf(leaky02(a.x + ad.x));
            w.y = __expf(leaky02(a.y + ad.y));
            w.z = __expf(leaky02(a.z + ad.z));
            w.w = __expf(leaky02(a.w + ad.w));
            *(float4*)(ew_sm + tid * 4) = w;
        }
        __syncthreads();

        const int P = 4;
        float2 v[P];
#pragma unroll
        for (int j = 0; j < P; j++)
            if (j < cn) v[j] = __half22float2(lin[(size_t)s_sm[j] * (HC0/2) + tid]);

        for (int i = 0; i < cn; i++) {
            float  w  = ew_sm[i * 4 + h];
            float2 vv = v[i & (P - 1)];
            int nx = i + P;
            if (nx < cn)
                v[i & (P - 1)] = __half22float2(lin[(size_t)s_sm[nx] * (HC0/2) + tid]);
            den  += w;
            acc.x = fmaf(w, vv.x, acc.x);
            acc.y = fmaf(w, vv.y, acc.y);
        }
    }

    float inv = 1.f / (den + 1e-16f);
    float2 bb = *(const float2*)(b0 + tid * 2);
    float2 o;
    o.x = fmaxf(acc.x * inv + bb.x, 0.f);
    o.y = fmaxf(acc.y * inv + bb.y, 0.f);
    *(float2*)(g_feat + (size_t)d * HC0 + tid * 2) = o;
}

// ---------------- aggregation layer 1: warp per dst, inline weights ----------------
__global__ void __launch_bounds__(256)
k_agg1(const float* __restrict__ b1, float* __restrict__ out)
{
    const int d    = (blockIdx.x * blockDim.x + threadIdx.x) >> 5;
    const int lane = threadIdx.x & 31;
    if (d >= NN) return;

    const int beg = g_row[d];
    const int n   = g_row[d + 1] - beg;
    const float ad = g_ad1[d];

    float2 acc = make_float2(0.f, 0.f);
    float  den = 0.f;
    const __half2* lin = (const __half2*)g_lin1h;

    for (int base = 0; base < n; base += 32) {
        const int m = min(32, n - base);
        int   s32 = 0;
        float w32 = 0.f;
        if (lane < m) {
            s32 = g_srcl[beg + base + lane];
            w32 = __expf(leaky02(g_as1[s32] + ad));
        }
        const int P = 4;
        float2 v[P];
#pragma unroll
        for (int j = 0; j < P; j++)
            if (j < m) {
                int s = __shfl_sync(0xffffffffu, s32, j);
                v[j] = __half22float2(lin[(size_t)s * (HC1/2) + lane]);
            }
        for (int i = 0; i < m; i++) {
            float  w  = __shfl_sync(0xffffffffu, w32, i);
            float2 vv = v[i & (P - 1)];
            int nx = i + P;
            if (nx < m) {
                int s = __shfl_sync(0xffffffffu, s32, nx);
                v[i & (P - 1)] = __half22float2(lin[(size_t)s * (HC1/2) + lane]);
            }
            den  += w;
            acc.x = fmaf(w, vv.x, acc.x);
            acc.y = fmaf(w, vv.y, acc.y);
        }
    }

    float inv = 1.f / (den + 1e-16f);
    float2 bb = *(const float2*)(b1 + lane * 2);
    float2 o;
    o.x = acc.x * inv + bb.x;
    o.y = acc.y * inv + bb.y;
    *(float2*)(out + (size_t)d * HC1 + lane * 2) = o;
}

// ---------------- launch ----------------
extern "C" void kernel_launch(void* const* d_in, const int* in_sizes, int n_in,
                              void* d_out, int out_size)
{
    const float* x      = (const float*)d_in[0];
    const int*   ei     = (const int*)  d_in[1];
    const float* W0     = (const float*)d_in[2];
    const float* att_s0 = (const float*)d_in[3];
    const float* att_d0 = (const float*)d_in[4];
    const float* b0     = (const float*)d_in[5];
    const float* W1     = (const float*)d_in[6];
    const float* att_s1 = (const float*)d_in[7];
    const float* att_d1 = (const float*)d_in[8];
    const float* b1     = (const float*)d_in[9];

    const int E    = in_sizes[1] / 2;
    const int Etot = E + NN;

    __half *p_lin0h, *p_lin1h;
    float  *p_feat, *p_as0, *p_ad0, *p_as1, *p_ad1;
    cudaGetSymbolAddress((void**)&p_lin0h, g_lin0h);
    cudaGetSymbolAddress((void**)&p_lin1h, g_lin1h);
    cudaGetSymbolAddress((void**)&p_feat,  g_feat);
    cudaGetSymbolAddress((void**)&p_as0,   g_as0);
    cudaGetSymbolAddress((void**)&p_ad0,   g_ad0);
    cudaGetSymbolAddress((void**)&p_as1,   g_as1);
    cudaGetSymbolAddress((void**)&p_ad1,   g_ad1);

    static cudaStream_t sB = nullptr;
    static cudaEvent_t  evFork = nullptr, evJoin = nullptr;
    if (sB == nullptr) {
        cudaStreamCreateWithFlags(&sB, cudaStreamNonBlocking);
        cudaEventCreateWithFlags(&evFork, cudaEventDisableTiming);
        cudaEventCreateWithFlags(&evJoin, cudaEventDisableTiming);
    }

    const int TB = 256;

    // ---- fork: CSR build on side stream, concurrent with GEMM0 ----
    cudaEventRecord(evFork, 0);
    cudaStreamWaitEvent(sB, evFork, 0);
    k_zero_deg<<<(NN + TB - 1) / TB, TB, 0, sB>>>();
    k_hist<<<(Etot + TB - 1) / TB, TB, 0, sB>>>(ei, E, Etot);
    k_scan<<<1, 1024, 0, sB>>>();
    k_scatter<<<(Etot + TB - 1) / TB, TB, 0, sB>>>(ei, E, Etot);
    cudaEventRecord(evJoin, sB);

    // ---- layer 0 GEMM ----
    {
        dim3 grid((NN + 127) / 128, HC0 / 64);
        gemm_nt<128, 64, 32, 8, 8><<<grid, 128>>>(x, W0, p_lin0h, NN, HC0, F0,
                                                  att_s0, att_d0, p_as0, p_ad0);
    }

    cudaStreamWaitEvent(0, evJoin, 0);
    k_agg0<<<NN, 128>>>(b0);

    // ---- layer 1 ----
    {
        dim3 grid((NN + 127) / 128, HC1 / 64);
        gemm_nt<128, 64, 32, 8, 8><<<grid, 128>>>(p_feat, W1, p_lin1h, NN, HC1, HC0,
                                                  att_s1, att_d1, p_as1, p_ad1);
    }
    k_agg1<<<(NN * 32 + TB - 1) / TB, TB>>>(b1, (float*)d_out);
}

// round 6
// speedup vs baseline: 1.0545x; 1.0545x over previous
#include <cuda_runtime.h>
#include <cstdint>
#include <math.h>

// ---------------- problem constants ----------------
#define NN    50000
#define F0    128
#define H0    4
#define HC0   256
#define HC1   64
#define EMAX  900000
#define AGGW  8      // warps per block in agg0

// ---------------- scratch ----------------
__device__ float g_lin0[(size_t)NN * HC0];
__device__ float g_feat[(size_t)NN * HC0];
__device__ float g_lin1[(size_t)NN * HC1];
__device__ float g_as0 [NN * H0];
__device__ float g_ad0 [NN * H0];
__device__ float g_as1 [NN];
__device__ float g_ad1 [NN];
__device__ int   g_deg [NN];
__device__ int   g_row [NN + 1];
__device__ int   g_cur [NN];
__device__ int   g_srcl[EMAX];

__device__ __forceinline__ float leaky02(float v) { return v > 0.0f ? v : 0.2f * v; }

__device__ __forceinline__ void edge_sd(const int* __restrict__ ei, int e, int E, int& s, int& d) {
    if (e < E) { s = ei[e]; d = ei[E + e]; } else { s = e - E; d = e - E; }
}

// ---------------- CSR build ----------------
__global__ void k_zero_deg() {
    int i = blockIdx.x * blockDim.x + threadIdx.x;
    if (i < NN) g_deg[i] = 0;
}
__global__ void k_hist(const int* __restrict__ ei, int E, int Etot) {
    int e = blockIdx.x * blockDim.x + threadIdx.x;
    if (e >= Etot) return;
    int s, d; edge_sd(ei, e, E, s, d);
    atomicAdd(&g_deg[d], 1);
}
__global__ void k_scan() {
    __shared__ int ssum[1024];
    const int t  = threadIdx.x;
    const int CH = (NN + 1023) / 1024;
    int beg = t * CH;
    int end = min(beg + CH, NN);
    int s = 0;
    for (int j = beg; j < end; j++) s += g_deg[j];
    ssum[t] = s;
    __syncthreads();
    for (int o = 1; o < 1024; o <<= 1) {
        int v = (t >= o) ? ssum[t - o] : 0;
        __syncthreads();
        ssum[t] += v;
        __syncthreads();
    }
    int run = (t == 0) ? 0 : ssum[t - 1];
    for (int j = beg; j < end; j++) {
        int dv = g_deg[j];
        g_row[j] = run;
        g_cur[j] = run;
        run += dv;
    }
    if (t == 1023) g_row[NN] = run;
}
__global__ void k_scatter(const int* __restrict__ ei, int E, int Etot) {
    int e = blockIdx.x * blockDim.x + threadIdx.x;
    if (e >= Etot) return;
    int s, d; edge_sd(ei, e, E, s, d);
    int pos = atomicAdd(&g_cur[d], 1);
    g_srcl[pos] = s;
}

// ---------------- GEMM (fp32x2 packed FMA) with fused attention-coef epilogue ----------------
template<int BM, int BN, int BK, int TM, int TN>
__global__ void __launch_bounds__((BM/TM)*(BN/TN))
gemm_nt(const float* __restrict__ A, const float* __restrict__ B,
        float* __restrict__ C, int M, int Nc, int K,
        const float* __restrict__ att_s, const float* __restrict__ att_d,
        float* __restrict__ as_out, float* __restrict__ ad_out)
{
    constexpr int THREADS = (BM/TM)*(BN/TN);
    constexpr int BMP = BM + 4;
    constexpr int BNP = BN + 4;
    __shared__ __align__(16) float As[BK][BMP];
    __shared__ __align__(16) float Bs[BK][BNP];

    const int tid = threadIdx.x;
    const int tx  = tid % (BN/TN);
    const int ty  = tid / (BN/TN);
    const int rowBase = blockIdx.x * BM;
    const int colBase = blockIdx.y * BN;

    unsigned long long acc2[TM][TN/2];
#pragma unroll
    for (int i = 0; i < TM; i++)
#pragma unroll
        for (int j = 0; j < TN/2; j++) acc2[i][j] = 0ull;

    for (int k0 = 0; k0 < K; k0 += BK) {
        constexpr int AF4 = BM * BK / 4;
#pragma unroll
        for (int i = 0; i < AF4 / THREADS; i++) {
            int f  = tid + i * THREADS;
            int r  = f / (BK/4);
            int c4 = f % (BK/4);
            float4 v = make_float4(0.f, 0.f, 0.f, 0.f);
            int gr = rowBase + r;
            if (gr < M) v = *(const float4*)(A + (size_t)gr * K + k0 + c4 * 4);
            As[c4*4+0][r] = v.x; As[c4*4+1][r] = v.y;
            As[c4*4+2][r] = v.z; As[c4*4+3][r] = v.w;
        }
        constexpr int BF4 = BN * BK / 4;
#pragma unroll
        for (int i = 0; i < BF4 / THREADS; i++) {
            int f  = tid + i * THREADS;
            int r  = f / (BK/4);
            int c4 = f % (BK/4);
            float4 v = *(const float4*)(B + (size_t)(colBase + r) * K + k0 + c4 * 4);
            Bs[c4*4+0][r] = v.x; Bs[c4*4+1][r] = v.y;
            Bs[c4*4+2][r] = v.z; Bs[c4*4+3][r] = v.w;
        }
        __syncthreads();

#pragma unroll
        for (int k = 0; k < BK; k++) {
            float a[TM];
            const float4* ap = (const float4*)&As[k][ty * TM];
            ((float4*)a)[0] = ap[0]; ((float4*)a)[1] = ap[1];
            unsigned long long b2[TN/2];
            const unsigned long long* bp = (const unsigned long long*)&Bs[k][tx * TN];
#pragma unroll
            for (int j = 0; j < TN/2; j++) b2[j] = bp[j];
#pragma unroll
            for (int i = 0; i < TM; i++) {
                unsigned long long a2;
                asm("mov.b64 %0, {%1, %1};" : "=l"(a2) : "f"(a[i]));
#pragma unroll
                for (int j = 0; j < TN/2; j++)
                    asm("fma.rn.f32x2 %0, %1, %2, %0;"
                        : "+l"(acc2[i][j]) : "l"(a2), "l"(b2[j]));
            }
        }
        __syncthreads();
    }

    // ---- store C ----
#pragma unroll
    for (int i = 0; i < TM; i++) {
        int gr = rowBase + ty * TM + i;
        if (gr < M) {
            const float* af = (const float*)acc2[i];
            float* cp = C + (size_t)gr * Nc + colBase + tx * TN;
            *(float4*)(cp)     = make_float4(af[0], af[1], af[2], af[3]);
            *(float4*)(cp + 4) = make_float4(af[4], af[5], af[6], af[7]);
        }
    }

    // ---- fused attention coefficients (BN==64 == one head) ----
    {
        const int Hh   = Nc >> 6;
        const int head = colBase >> 6;
        float asv[TN], adv[TN];
#pragma unroll
        for (int j = 0; j < TN; j++) {
            asv[j] = att_s[colBase + tx * TN + j];
            adv[j] = att_d[colBase + tx * TN + j];
        }
#pragma unroll
        for (int i = 0; i < TM; i++) {
            const float* af = (const float*)acc2[i];
            float ps = 0.f, pd = 0.f;
#pragma unroll
            for (int j = 0; j < TN; j++) {
                ps = fmaf(af[j], asv[j], ps);
                pd = fmaf(af[j], adv[j], pd);
            }
#pragma unroll
            for (int o = 1; o < (BN/TN); o <<= 1) {
                ps += __shfl_xor_sync(0xffffffffu, ps, o);
                pd += __shfl_xor_sync(0xffffffffu, pd, o);
            }
            int gr = rowBase + ty * TM + i;
            if (tx == 0 && gr < M) {
                as_out[gr * Hh + head] = ps;
                ad_out[gr * Hh + head] = pd;
            }
        }
    }
}

// ---------------- aggregation layer 0: warp per dst, float4 gathers ----------------
__global__ void __launch_bounds__(AGGW * 32)
k_agg0(const float* __restrict__ b0)
{
    const int d    = (blockIdx.x * blockDim.x + threadIdx.x) >> 5;
    const int lane = threadIdx.x & 31;
    const int wl   = threadIdx.x >> 5;
    if (d >= NN) return;

    __shared__ int   s_sm[AGGW][32];
    __shared__ float w_sm[AGGW][32 * 4];

    const int beg = g_row[d];
    const int n   = g_row[d + 1] - beg;
    const float4 ad = *(const float4*)(g_ad0 + d * 4);
    const int h     = lane >> 3;       // head for this lane's 8 channels
    const int choff = lane * 8;

    float4 accA = make_float4(0.f, 0.f, 0.f, 0.f);
    float4 accB = make_float4(0.f, 0.f, 0.f, 0.f);
    float  den  = 0.f;

    for (int base = 0; base < n; base += 32) {
        const int m = min(32, n - base);
        __syncwarp();
        if (lane < m) {
            int s = g_srcl[beg + base + lane];
            s_sm[wl][lane] = s;
            float4 a = *(const float4*)(g_as0 + s * 4);
            float4 w4;
            w4.x = __expf(leaky02(a.x + ad.x));
            w4.y = __expf(leaky02(a.y + ad.y));
            w4.z = __expf(leaky02(a.z + ad.z));
            w4.w = __expf(leaky02(a.w + ad.w));
            *(float4*)&w_sm[wl][lane * 4] = w4;
        }
        __syncwarp();

        const int P = 2;
        float4 vA[P], vB[P];
#pragma unroll
        for (int j = 0; j < P; j++)
            if (j < m) {
                const float* rp = g_lin0 + (size_t)s_sm[wl][j] * HC0 + choff;
                vA[j] = *(const float4*)rp;
                vB[j] = *(const float4*)(rp + 4);
            }

        for (int i = 0; i < m; i++) {
            float  w  = w_sm[wl][i * 4 + h];
            float4 a0 = vA[i & (P - 1)];
            float4 b0v = vB[i & (P - 1)];
            int nx = i + P;
            if (nx < m) {
                const float* rp = g_lin0 + (size_t)s_sm[wl][nx] * HC0 + choff;
                vA[i & (P - 1)] = *(const float4*)rp;
                vB[i & (P - 1)] = *(const float4*)(rp + 4);
            }
            den   += w;
            accA.x = fmaf(w, a0.x, accA.x);
            accA.y = fmaf(w, a0.y, accA.y);
            accA.z = fmaf(w, a0.z, accA.z);
            accA.w = fmaf(w, a0.w, accA.w);
            accB.x = fmaf(w, b0v.x, accB.x);
            accB.y = fmaf(w, b0v.y, accB.y);
            accB.z = fmaf(w, b0v.z, accB.z);
            accB.w = fmaf(w, b0v.w, accB.w);
        }
    }

    const float inv = 1.f / (den + 1e-16f);
    float4 bbA = *(const float4*)(b0 + choff);
    float4 bbB = *(const float4*)(b0 + choff + 4);
    float4 oA, oB;
    oA.x = fmaxf(accA.x * inv + bbA.x, 0.f);
    oA.y = fmaxf(accA.y * inv + bbA.y, 0.f);
    oA.z = fmaxf(accA.z * inv + bbA.z, 0.f);
    oA.w = fmaxf(accA.w * inv + bbA.w, 0.f);
    oB.x = fmaxf(accB.x * inv + bbB.x, 0.f);
    oB.y = fmaxf(accB.y * inv + bbB.y, 0.f);
    oB.z = fmaxf(accB.z * inv + bbB.z, 0.f);
    oB.w = fmaxf(accB.w * inv + bbB.w, 0.f);
    float* op = g_feat + (size_t)d * HC0 + choff;
    *(float4*)(op)     = oA;
    *(float4*)(op + 4) = oB;
}

// ---------------- aggregation layer 1: warp per dst, inline weights (fp32) ----------------
__global__ void __launch_bounds__(256)
k_agg1(const float* __restrict__ b1, float* __restrict__ out)
{
    const int d    = (blockIdx.x * blockDim.x + threadIdx.x) >> 5;
    const int lane = threadIdx.x & 31;
    if (d >= NN) return;

    const int beg = g_row[d];
    const int n   = g_row[d + 1] - beg;
    const float ad = g_ad1[d];

    float2 acc = make_float2(0.f, 0.f);
    float  den = 0.f;
    const int choff = lane * 2;

    for (int base = 0; base < n; base += 32) {
        const int m = min(32, n - base);
        int   s32 = 0;
        float w32 = 0.f;
        if (lane < m) {
            s32 = g_srcl[beg + base + lane];
            w32 = __expf(leaky02(g_as1[s32] + ad));
        }
        const int P = 4;
        float2 v[P];
#pragma unroll
        for (int j = 0; j < P; j++)
            if (j < m) {
                int s = __shfl_sync(0xffffffffu, s32, j);
                v[j] = *(const float2*)(g_lin1 + (size_t)s * HC1 + choff);
            }
        for (int i = 0; i < m; i++) {
            float  w  = __shfl_sync(0xffffffffu, w32, i);
            float2 vv = v[i & (P - 1)];
            int nx = i + P;
            if (nx < m) {
                int s = __shfl_sync(0xffffffffu, s32, nx);
                v[i & (P - 1)] = *(const float2*)(g_lin1 + (size_t)s * HC1 + choff);
            }
            den  += w;
            acc.x = fmaf(w, vv.x, acc.x);
            acc.y = fmaf(w, vv.y, acc.y);
        }
    }

    float inv = 1.f / (den + 1e-16f);
    float2 bb = *(const float2*)(b1 + choff);
    float2 o;
    o.x = acc.x * inv + bb.x;
    o.y = acc.y * inv + bb.y;
    *(float2*)(out + (size_t)d * HC1 + choff) = o;
}

// ---------------- launch ----------------
extern "C" void kernel_launch(void* const* d_in, const int* in_sizes, int n_in,
                              void* d_out, int out_size)
{
    const float* x      = (const float*)d_in[0];
    const int*   ei     = (const int*)  d_in[1];
    const float* W0     = (const float*)d_in[2];
    const float* att_s0 = (const float*)d_in[3];
    const float* att_d0 = (const float*)d_in[4];
    const float* b0     = (const float*)d_in[5];
    const float* W1     = (const float*)d_in[6];
    const float* att_s1 = (const float*)d_in[7];
    const float* att_d1 = (const float*)d_in[8];
    const float* b1     = (const float*)d_in[9];

    const int E    = in_sizes[1] / 2;
    const int Etot = E + NN;

    float *p_lin0, *p_feat, *p_lin1, *p_as0, *p_ad0, *p_as1, *p_ad1;
    cudaGetSymbolAddress((void**)&p_lin0, g_lin0);
    cudaGetSymbolAddress((void**)&p_feat, g_feat);
    cudaGetSymbolAddress((void**)&p_lin1, g_lin1);
    cudaGetSymbolAddress((void**)&p_as0,  g_as0);
    cudaGetSymbolAddress((void**)&p_ad0,  g_ad0);
    cudaGetSymbolAddress((void**)&p_as1,  g_as1);
    cudaGetSymbolAddress((void**)&p_ad1,  g_ad1);

    static cudaStream_t sB = nullptr;
    static cudaEvent_t  evFork = nullptr, evJoin = nullptr;
    if (sB == nullptr) {
        cudaStreamCreateWithFlags(&sB, cudaStreamNonBlocking);
        cudaEventCreateWithFlags(&evFork, cudaEventDisableTiming);
        cudaEventCreateWithFlags(&evJoin, cudaEventDisableTiming);
    }

    const int TB = 256;

    // ---- fork: CSR build on side stream, concurrent with GEMM0 ----
    cudaEventRecord(evFork, 0);
    cudaStreamWaitEvent(sB, evFork, 0);
    k_zero_deg<<<(NN + TB - 1) / TB, TB, 0, sB>>>();
    k_hist<<<(Etot + TB - 1) / TB, TB, 0, sB>>>(ei, E, Etot);
    k_scan<<<1, 1024, 0, sB>>>();
    k_scatter<<<(Etot + TB - 1) / TB, TB, 0, sB>>>(ei, E, Etot);
    cudaEventRecord(evJoin, sB);

    // ---- layer 0 GEMM ----
    {
        dim3 grid((NN + 127) / 128, HC0 / 64);
        gemm_nt<128, 64, 32, 8, 8><<<grid, 128>>>(x, W0, p_lin0, NN, HC0, F0,
                                                  att_s0, att_d0, p_as0, p_ad0);
    }

    cudaStreamWaitEvent(0, evJoin, 0);
    k_agg0<<<(NN * 32 + AGGW * 32 - 1) / (AGGW * 32), AGGW * 32>>>(b0);

    // ---- layer 1 ----
    {
        dim3 grid((NN + 127) / 128, HC1 / 64);
        gemm_nt<128, 64, 32, 8, 8><<<grid, 128>>>(p_feat, W1, p_lin1, NN, HC1, HC0,
                                                  att_s1, att_d1, p_as1, p_ad1);
    }
    k_agg1<<<(NN * 32 + TB - 1) / TB, TB>>>(b1, (float*)d_out);
}

// round 7
// speedup vs baseline: 1.2713x; 1.2056x over previous
#include <cuda_runtime.h>
#include <cstdint>
#include <math.h>

// ---------------- problem constants ----------------
#define NN    50000
#define F0    128
#define H0    4
#define HC0   256
#define HC1   64
#define EMAX  900000
#define AGGW  8

// ---------------- scratch ----------------
__device__ float g_lin0[(size_t)NN * HC0];
__device__ float g_feat[(size_t)NN * HC0];
__device__ float g_lin1[(size_t)NN * HC1];
__device__ float g_as0 [NN * H0];
__device__ float g_ad0 [NN * H0];
__device__ float g_as1 [NN];
__device__ float g_ad1 [NN];
__device__ int   g_deg [NN];
__device__ int   g_row [NN + 1];
__device__ int   g_cur [NN];
__device__ int   g_srcl[EMAX];

__device__ __forceinline__ float leaky02(float v) { return v > 0.0f ? v : 0.2f * v; }

__device__ __forceinline__ unsigned tf32_of(float x) {
    unsigned u;
    asm("cvt.rna.tf32.f32 %0, %1;" : "=r"(u) : "f"(x));
    return u;
}

__device__ __forceinline__ void edge_sd(const int* __restrict__ ei, int e, int E, int& s, int& d) {
    if (e < E) { s = ei[e]; d = ei[E + e]; } else { s = e - E; d = e - E; }
}

// ---------------- CSR build ----------------
__global__ void k_zero_deg() {
    int i = blockIdx.x * blockDim.x + threadIdx.x;
    if (i < NN) g_deg[i] = 0;
}
__global__ void k_hist(const int* __restrict__ ei, int E, int Etot) {
    int e = blockIdx.x * blockDim.x + threadIdx.x;
    if (e >= Etot) return;
    int s, d; edge_sd(ei, e, E, s, d);
    atomicAdd(&g_deg[d], 1);
}
__global__ void k_scan() {
    __shared__ int ssum[1024];
    const int t  = threadIdx.x;
    const int CH = (NN + 1023) / 1024;
    int beg = t * CH;
    int end = min(beg + CH, NN);
    int s = 0;
    for (int j = beg; j < end; j++) s += g_deg[j];
    ssum[t] = s;
    __syncthreads();
    for (int o = 1; o < 1024; o <<= 1) {
        int v = (t >= o) ? ssum[t - o] : 0;
        __syncthreads();
        ssum[t] += v;
        __syncthreads();
    }
    int run = (t == 0) ? 0 : ssum[t - 1];
    for (int j = beg; j < end; j++) {
        int dv = g_deg[j];
        g_row[j] = run;
        g_cur[j] = run;
        run += dv;
    }
    if (t == 1023) g_row[NN] = run;
}
__global__ void k_scatter(const int* __restrict__ ei, int E, int Etot) {
    int e = blockIdx.x * blockDim.x + threadIdx.x;
    if (e >= Etot) return;
    int s, d; edge_sd(ei, e, E, s, d);
    int pos = atomicAdd(&g_cur[d], 1);
    g_srcl[pos] = s;
}

// ---------------- tf32 tensor-core GEMM + fused attention-coef epilogue ----------------
// C[M,Nc] = A[M,K] * B[Nc,K]^T.  Block tile 128x64 (8 warps, warp = 16 rows x 64 cols).
// BN == 64 == one head; epilogue computes as/ad per row via quad reduction.
#define TBK 32
__global__ void __launch_bounds__(256)
gemm_tf32(const float* __restrict__ A, const float* __restrict__ B,
          float* __restrict__ C, int M, int Nc, int K,
          const float* __restrict__ att_s, const float* __restrict__ att_d,
          float* __restrict__ as_out, float* __restrict__ ad_out)
{
    __shared__ unsigned As[128][TBK + 4];   // 18.4 KB
    __shared__ unsigned Bs[64][TBK + 4];    //  9.2 KB

    const int tid  = threadIdx.x;
    const int lane = tid & 31;
    const int warp = tid >> 5;
    const int g    = lane >> 2;     // group (row within 8)
    const int q    = lane & 3;      // thread-in-group
    const int rowBase = blockIdx.x * 128;
    const int colBase = blockIdx.y * 64;
    const int warpRow = warp * 16;

    float acc[8][4];
#pragma unroll
    for (int t = 0; t < 8; t++)
#pragma unroll
        for (int j = 0; j < 4; j++) acc[t][j] = 0.f;

    for (int k0 = 0; k0 < K; k0 += TBK) {
        // ---- fill A tile (128 x 32), 4 float4 per thread ----
#pragma unroll
        for (int i = 0; i < 4; i++) {
            int f  = tid + i * 256;
            int r  = f >> 3;
            int c4 = (f & 7) * 4;
            float4 v = make_float4(0.f, 0.f, 0.f, 0.f);
            int gr = rowBase + r;
            if (gr < M) v = *(const float4*)(A + (size_t)gr * K + k0 + c4);
            As[r][c4+0] = tf32_of(v.x); As[r][c4+1] = tf32_of(v.y);
            As[r][c4+2] = tf32_of(v.z); As[r][c4+3] = tf32_of(v.w);
        }
        // ---- fill B tile (64 x 32), 2 float4 per thread ----
#pragma unroll
        for (int i = 0; i < 2; i++) {
            int f  = tid + i * 256;
            int r  = f >> 3;
            int c4 = (f & 7) * 4;
            float4 v = *(const float4*)(B + (size_t)(colBase + r) * K + k0 + c4);
            Bs[r][c4+0] = tf32_of(v.x); Bs[r][c4+1] = tf32_of(v.y);
            Bs[r][c4+2] = tf32_of(v.z); Bs[r][c4+3] = tf32_of(v.w);
        }
        __syncthreads();

#pragma unroll
        for (int kk = 0; kk < TBK; kk += 8) {
            unsigned a0 = As[warpRow + g    ][kk + q];
            unsigned a1 = As[warpRow + g + 8][kk + q];
            unsigned a2 = As[warpRow + g    ][kk + q + 4];
            unsigned a3 = As[warpRow + g + 8][kk + q + 4];
#pragma unroll
            for (int t = 0; t < 8; t++) {
                unsigned b0 = Bs[t * 8 + g][kk + q];
                unsigned b1 = Bs[t * 8 + g][kk + q + 4];
                asm("mma.sync.aligned.m16n8k8.row.col.f32.tf32.tf32.f32 "
                    "{%0,%1,%2,%3}, {%4,%5,%6,%7}, {%8,%9}, {%0,%1,%2,%3};"
                    : "+f"(acc[t][0]), "+f"(acc[t][1]), "+f"(acc[t][2]), "+f"(acc[t][3])
                    : "r"(a0), "r"(a1), "r"(a2), "r"(a3), "r"(b0), "r"(b1));
            }
        }
        __syncthreads();
    }

    // ---- store C ----
    const int r0 = rowBase + warpRow + g;
    const int r1 = r0 + 8;
#pragma unroll
    for (int t = 0; t < 8; t++) {
        int col = colBase + t * 8 + q * 2;
        if (r0 < M) *(float2*)(C + (size_t)r0 * Nc + col) = make_float2(acc[t][0], acc[t][1]);
        if (r1 < M) *(float2*)(C + (size_t)r1 * Nc + col) = make_float2(acc[t][2], acc[t][3]);
    }

    // ---- fused attention coefficients ----
    {
        float ps0 = 0.f, pd0 = 0.f, ps1 = 0.f, pd1 = 0.f;
#pragma unroll
        for (int t = 0; t < 8; t++) {
            int col = colBase + t * 8 + q * 2;
            float s0 = att_s[col], s1 = att_s[col + 1];
            float d0 = att_d[col], d1 = att_d[col + 1];
            ps0 = fmaf(acc[t][0], s0, fmaf(acc[t][1], s1, ps0));
            pd0 = fmaf(acc[t][0], d0, fmaf(acc[t][1], d1, pd0));
            ps1 = fmaf(acc[t][2], s0, fmaf(acc[t][3], s1, ps1));
            pd1 = fmaf(acc[t][2], d0, fmaf(acc[t][3], d1, pd1));
        }
#pragma unroll
        for (int o = 1; o < 4; o <<= 1) {
            ps0 += __shfl_xor_sync(0xffffffffu, ps0, o);
            pd0 += __shfl_xor_sync(0xffffffffu, pd0, o);
            ps1 += __shfl_xor_sync(0xffffffffu, ps1, o);
            pd1 += __shfl_xor_sync(0xffffffffu, pd1, o);
        }
        const int Hh   = Nc >> 6;
        const int head = colBase >> 6;
        if (q == 0) {
            if (r0 < M) { as_out[r0 * Hh + head] = ps0; ad_out[r0 * Hh + head] = pd0; }
            if (r1 < M) { as_out[r1 * Hh + head] = ps1; ad_out[r1 * Hh + head] = pd1; }
        }
    }
}

// ---------------- aggregation layer 0: warp per dst, float4 gathers ----------------
__global__ void __launch_bounds__(AGGW * 32)
k_agg0(const float* __restrict__ b0)
{
    const int d    = (blockIdx.x * blockDim.x + threadIdx.x) >> 5;
    const int lane = threadIdx.x & 31;
    const int wl   = threadIdx.x >> 5;
    if (d >= NN) return;

    __shared__ int   s_sm[AGGW][32];
    __shared__ float w_sm[AGGW][32 * 4];

    const int beg = g_row[d];
    const int n   = g_row[d + 1] - beg;
    const float4 ad = *(const float4*)(g_ad0 + d * 4);
    const int h     = lane >> 3;
    const int choff = lane * 8;

    float4 accA = make_float4(0.f, 0.f, 0.f, 0.f);
    float4 accB = make_float4(0.f, 0.f, 0.f, 0.f);
    float  den  = 0.f;

    for (int base = 0; base < n; base += 32) {
        const int m = min(32, n - base);
        __syncwarp();
        if (lane < m) {
            int s = g_srcl[beg + base + lane];
            s_sm[wl][lane] = s;
            float4 a = *(const float4*)(g_as0 + s * 4);
            float4 w4;
            w4.x = __expf(leaky02(a.x + ad.x));
            w4.y = __expf(leaky02(a.y + ad.y));
            w4.z = __expf(leaky02(a.z + ad.z));
            w4.w = __expf(leaky02(a.w + ad.w));
            *(float4*)&w_sm[wl][lane * 4] = w4;
        }
        __syncwarp();

        const int P = 2;
        float4 vA[P], vB[P];
#pragma unroll
        for (int j = 0; j < P; j++)
            if (j < m) {
                const float* rp = g_lin0 + (size_t)s_sm[wl][j] * HC0 + choff;
                vA[j] = *(const float4*)rp;
                vB[j] = *(const float4*)(rp + 4);
            }

        for (int i = 0; i < m; i++) {
            float  w   = w_sm[wl][i * 4 + h];
            float4 a0  = vA[i & (P - 1)];
            float4 b0v = vB[i & (P - 1)];
            int nx = i + P;
            if (nx < m) {
                const float* rp = g_lin0 + (size_t)s_sm[wl][nx] * HC0 + choff;
                vA[i & (P - 1)] = *(const float4*)rp;
                vB[i & (P - 1)] = *(const float4*)(rp + 4);
            }
            den   += w;
            accA.x = fmaf(w, a0.x, accA.x);
            accA.y = fmaf(w, a0.y, accA.y);
            accA.z = fmaf(w, a0.z, accA.z);
            accA.w = fmaf(w, a0.w, accA.w);
            accB.x = fmaf(w, b0v.x, accB.x);
            accB.y = fmaf(w, b0v.y, accB.y);
            accB.z = fmaf(w, b0v.z, accB.z);
            accB.w = fmaf(w, b0v.w, accB.w);
        }
    }

    const float inv = 1.f / (den + 1e-16f);
    float4 bbA = *(const float4*)(b0 + choff);
    float4 bbB = *(const float4*)(b0 + choff + 4);
    float4 oA, oB;
    oA.x = fmaxf(accA.x * inv + bbA.x, 0.f);
    oA.y = fmaxf(accA.y * inv + bbA.y, 0.f);
    oA.z = fmaxf(accA.z * inv + bbA.z, 0.f);
    oA.w = fmaxf(accA.w * inv + bbA.w, 0.f);
    oB.x = fmaxf(accB.x * inv + bbB.x, 0.f);
    oB.y = fmaxf(accB.y * inv + bbB.y, 0.f);
    oB.z = fmaxf(accB.z * inv + bbB.z, 0.f);
    oB.w = fmaxf(accB.w * inv + bbB.w, 0.f);
    float* op = g_feat + (size_t)d * HC0 + choff;
    *(float4*)(op)     = oA;
    *(float4*)(op + 4) = oB;
}

// ---------------- aggregation layer 1: warp per dst ----------------
__global__ void __launch_bounds__(256)
k_agg1(const float* __restrict__ b1, float* __restrict__ out)
{
    const int d    = (blockIdx.x * blockDim.x + threadIdx.x) >> 5;
    const int lane = threadIdx.x & 31;
    if (d >= NN) return;

    const int beg = g_row[d];
    const int n   = g_row[d + 1] - beg;
    const float ad = g_ad1[d];

    float2 acc = make_float2(0.f, 0.f);
    float  den = 0.f;
    const int choff = lane * 2;

    for (int base = 0; base < n; base += 32) {
        const int m = min(32, n - base);
        int   s32 = 0;
        float w32 = 0.f;
        if (lane < m) {
            s32 = g_srcl[beg + base + lane];
            w32 = __expf(leaky02(g_as1[s32] + ad));
        }
        const int P = 4;
        float2 v[P];
#pragma unroll
        for (int j = 0; j < P; j++)
            if (j < m) {
                int s = __shfl_sync(0xffffffffu, s32, j);
                v[j] = *(const float2*)(g_lin1 + (size_t)s * HC1 + choff);
            }
        for (int i = 0; i < m; i++) {
            float  w  = __shfl_sync(0xffffffffu, w32, i);
            float2 vv = v[i & (P - 1)];
            int nx = i + P;
            if (nx < m) {
                int s = __shfl_sync(0xffffffffu, s32, nx);
                v[i & (P - 1)] = *(const float2*)(g_lin1 + (size_t)s * HC1 + choff);
            }
            den  += w;
            acc.x = fmaf(w, vv.x, acc.x);
            acc.y = fmaf(w, vv.y, acc.y);
        }
    }

    float inv = 1.f / (den + 1e-16f);
    float2 bb = *(const float2*)(b1 + choff);
    float2 o;
    o.x = acc.x * inv + bb.x;
    o.y = acc.y * inv + bb.y;
    *(float2*)(out + (size_t)d * HC1 + choff) = o;
}

// ---------------- launch ----------------
extern "C" void kernel_launch(void* const* d_in, const int* in_sizes, int n_in,
                              void* d_out, int out_size)
{
    const float* x      = (const float*)d_in[0];
    const int*   ei     = (const int*)  d_in[1];
    const float* W0     = (const float*)d_in[2];
    const float* att_s0 = (const float*)d_in[3];
    const float* att_d0 = (const float*)d_in[4];
    const float* b0     = (const float*)d_in[5];
    const float* W1     = (const float*)d_in[6];
    const float* att_s1 = (const float*)d_in[7];
    const float* att_d1 = (const float*)d_in[8];
    const float* b1     = (const float*)d_in[9];

    const int E    = in_sizes[1] / 2;
    const int Etot = E + NN;

    float *p_lin0, *p_feat, *p_lin1, *p_as0, *p_ad0, *p_as1, *p_ad1;
    cudaGetSymbolAddress((void**)&p_lin0, g_lin0);
    cudaGetSymbolAddress((void**)&p_feat, g_feat);
    cudaGetSymbolAddress((void**)&p_lin1, g_lin1);
    cudaGetSymbolAddress((void**)&p_as0,  g_as0);
    cudaGetSymbolAddress((void**)&p_ad0,  g_ad0);
    cudaGetSymbolAddress((void**)&p_as1,  g_as1);
    cudaGetSymbolAddress((void**)&p_ad1,  g_ad1);

    static cudaStream_t sB = nullptr;
    static cudaEvent_t  evFork = nullptr, evJoin = nullptr;
    if (sB == nullptr) {
        cudaStreamCreateWithFlags(&sB, cudaStreamNonBlocking);
        cudaEventCreateWithFlags(&evFork, cudaEventDisableTiming);
        cudaEventCreateWithFlags(&evJoin, cudaEventDisableTiming);
    }

    const int TB = 256;

    // ---- fork: CSR build on side stream, concurrent with GEMM0 ----
    cudaEventRecord(evFork, 0);
    cudaStreamWaitEvent(sB, evFork, 0);
    k_zero_deg<<<(NN + TB - 1) / TB, TB, 0, sB>>>();
    k_hist<<<(Etot + TB - 1) / TB, TB, 0, sB>>>(ei, E, Etot);
    k_scan<<<1, 1024, 0, sB>>>();
    k_scatter<<<(Etot + TB - 1) / TB, TB, 0, sB>>>(ei, E, Etot);
    cudaEventRecord(evJoin, sB);

    // ---- layer 0 GEMM (tf32 tensor cores) ----
    {
        dim3 grid((NN + 127) / 128, HC0 / 64);
        gemm_tf32<<<grid, 256>>>(x, W0, p_lin0, NN, HC0, F0,
                                 att_s0, att_d0, p_as0, p_ad0);
    }

    cudaStreamWaitEvent(0, evJoin, 0);
    k_agg0<<<(NN * 32 + AGGW * 32 - 1) / (AGGW * 32), AGGW * 32>>>(b0);

    // ---- layer 1 ----
    {
        dim3 grid((NN + 127) / 128, HC1 / 64);
        gemm_tf32<<<grid, 256>>>(p_feat, W1, p_lin1, NN, HC1, HC0,
                                 att_s1, att_d1, p_as1, p_ad1);
    }
    k_agg1<<<(NN * 32 + TB - 1) / TB, TB>>>(b1, (float*)d_out);
}

// round 9
// speedup vs baseline: 1.4632x; 1.1509x over previous
#include <cuda_runtime.h>
#include <cuda_fp16.h>
#include <cstdint>
#include <math.h>

// ---------------- problem constants ----------------
#define NN    50000
#define F0    128
#define H0    4
#define HC0   256
#define HC1   64
#define EMAX  900000
#define AGGW  8

// ---------------- scratch ----------------
__device__ __half g_lin0h[(size_t)NN * HC0];   // layer0 features, fp16
__device__ float  g_feat [(size_t)NN * HC0];   // relu(agg0+b0), fp32 (GEMM1 input)
__device__ float  g_lin1 [(size_t)NN * HC1];   // layer1 features, fp32
__device__ float  g_as0 [NN * H0];
__device__ float  g_ad0 [NN * H0];
__device__ float  g_as1 [NN];
__device__ float  g_ad1 [NN];
__device__ int    g_deg [NN];
__device__ int    g_row [NN + 1];
__device__ int    g_cur [NN];
__device__ int    g_srcl[EMAX];

__device__ __forceinline__ float leaky02(float v) { return v > 0.0f ? v : 0.2f * v; }

__device__ __forceinline__ unsigned tf32_of(float x) {
    unsigned u;
    asm("cvt.rna.tf32.f32 %0, %1;" : "=r"(u) : "f"(x));
    return u;
}

__device__ __forceinline__ void edge_sd(const int* __restrict__ ei, int e, int E, int& s, int& d) {
    if (e < E) { s = ei[e]; d = ei[E + e]; } else { s = e - E; d = e - E; }
}

// store helpers (fp32 or fp16 output from GEMM)
__device__ __forceinline__ void store2(float* p, float a, float b) {
    *(float2*)p = make_float2(a, b);
}
__device__ __forceinline__ void store2(__half* p, float a, float b) {
    *(__half2*)p = __floats2half2_rn(a, b);
}

// ---------------- CSR build ----------------
__global__ void k_zero_deg() {
    int i = blockIdx.x * blockDim.x + threadIdx.x;
    if (i < NN) g_deg[i] = 0;
}
// 4 edges per thread (strided) for MLP on the atomics
__global__ void k_hist(const int* __restrict__ ei, int E, int Etot, int T) {
    int t = blockIdx.x * blockDim.x + threadIdx.x;
    if (t >= T) return;               // tail guard: edge e=t is owned by thread t-T otherwise
#pragma unroll
    for (int i = 0; i < 4; i++) {
        int e = t + i * T;
        if (e < Etot) {
            int s, d; edge_sd(ei, e, E, s, d);
            atomicAdd(&g_deg[d], 1);
        }
    }
}
__global__ void k_scan() {
    __shared__ int ssum[1024];
    const int t  = threadIdx.x;
    const int CH = (NN + 1023) / 1024;
    int beg = t * CH;
    int end = min(beg + CH, NN);
    int s = 0;
    for (int j = beg; j < end; j++) s += g_deg[j];
    ssum[t] = s;
    __syncthreads();
    for (int o = 1; o < 1024; o <<= 1) {
        int v = (t >= o) ? ssum[t - o] : 0;
        __syncthreads();
        ssum[t] += v;
        __syncthreads();
    }
    int run = (t == 0) ? 0 : ssum[t - 1];
    for (int j = beg; j < end; j++) {
        int dv = g_deg[j];
        g_row[j] = run;
        g_cur[j] = run;
        run += dv;
    }
    if (t == 1023) g_row[NN] = run;
}
__global__ void k_scatter(const int* __restrict__ ei, int E, int Etot, int T) {
    int t = blockIdx.x * blockDim.x + threadIdx.x;
    if (t >= T) return;               // tail guard (see k_hist)
#pragma unroll
    for (int i = 0; i < 4; i++) {
        int e = t + i * T;
        if (e < Etot) {
            int s, d; edge_sd(ei, e, E, s, d);
            int pos = atomicAdd(&g_cur[d], 1);
            g_srcl[pos] = s;
        }
    }
}

// ---------------- tf32 tensor-core GEMM + fused attention-coef epilogue ----------------
// C[M,Nc] = A[M,K] * B[Nc,K]^T. Block 128x64 (8 warps, warp = 16 rows).
// BN == 64 == one head. Output type templated (fp16 for layer0, fp32 for layer1).
#define TBK 32
template<typename TO>
__global__ void __launch_bounds__(256)
gemm_tf32(const float* __restrict__ A, const float* __restrict__ B,
          TO* __restrict__ C, int M, int Nc, int K,
          const float* __restrict__ att_s, const float* __restrict__ att_d,
          float* __restrict__ as_out, float* __restrict__ ad_out)
{
    __shared__ unsigned As[128][TBK + 4];
    __shared__ unsigned Bs[64][TBK + 4];

    const int tid  = threadIdx.x;
    const int lane = tid & 31;
    const int warp = tid >> 5;
    const int g    = lane >> 2;
    const int q    = lane & 3;
    const int rowBase = blockIdx.x * 128;
    const int colBase = blockIdx.y * 64;
    const int warpRow = warp * 16;

    float acc[8][4];
#pragma unroll
    for (int t = 0; t < 8; t++)
#pragma unroll
        for (int j = 0; j < 4; j++) acc[t][j] = 0.f;

    for (int k0 = 0; k0 < K; k0 += TBK) {
#pragma unroll
        for (int i = 0; i < 4; i++) {
            int f  = tid + i * 256;
            int r  = f >> 3;
            int c4 = (f & 7) * 4;
            float4 v = make_float4(0.f, 0.f, 0.f, 0.f);
            int gr = rowBase + r;
            if (gr < M) v = *(const float4*)(A + (size_t)gr * K + k0 + c4);
            As[r][c4+0] = tf32_of(v.x); As[r][c4+1] = tf32_of(v.y);
            As[r][c4+2] = tf32_of(v.z); As[r][c4+3] = tf32_of(v.w);
        }
#pragma unroll
        for (int i = 0; i < 2; i++) {
            int f  = tid + i * 256;
            int r  = f >> 3;
            int c4 = (f & 7) * 4;
            float4 v = *(const float4*)(B + (size_t)(colBase + r) * K + k0 + c4);
            Bs[r][c4+0] = tf32_of(v.x); Bs[r][c4+1] = tf32_of(v.y);
            Bs[r][c4+2] = tf32_of(v.z); Bs[r][c4+3] = tf32_of(v.w);
        }
        __syncthreads();

#pragma unroll
        for (int kk = 0; kk < TBK; kk += 8) {
            unsigned a0 = As[warpRow + g    ][kk + q];
            unsigned a1 = As[warpRow + g + 8][kk + q];
            unsigned a2 = As[warpRow + g    ][kk + q + 4];
            unsigned a3 = As[warpRow + g + 8][kk + q + 4];
#pragma unroll
            for (int t = 0; t < 8; t++) {
                unsigned b0 = Bs[t * 8 + g][kk + q];
                unsigned b1 = Bs[t * 8 + g][kk + q + 4];
                asm("mma.sync.aligned.m16n8k8.row.col.f32.tf32.tf32.f32 "
                    "{%0,%1,%2,%3}, {%4,%5,%6,%7}, {%8,%9}, {%0,%1,%2,%3};"
                    : "+f"(acc[t][0]), "+f"(acc[t][1]), "+f"(acc[t][2]), "+f"(acc[t][3])
                    : "r"(a0), "r"(a1), "r"(a2), "r"(a3), "r"(b0), "r"(b1));
            }
        }
        __syncthreads();
    }

    const int r0 = rowBase + warpRow + g;
    const int r1 = r0 + 8;
#pragma unroll
    for (int t = 0; t < 8; t++) {
        int col = colBase + t * 8 + q * 2;
        if (r0 < M) store2(C + (size_t)r0 * Nc + col, acc[t][0], acc[t][1]);
        if (r1 < M) store2(C + (size_t)r1 * Nc + col, acc[t][2], acc[t][3]);
    }

    // fused attention coefficients
    {
        float ps0 = 0.f, pd0 = 0.f, ps1 = 0.f, pd1 = 0.f;
#pragma unroll
        for (int t = 0; t < 8; t++) {
            int col = colBase + t * 8 + q * 2;
            float s0 = att_s[col], s1 = att_s[col + 1];
            float d0 = att_d[col], d1 = att_d[col + 1];
            ps0 = fmaf(acc[t][0], s0, fmaf(acc[t][1], s1, ps0));
            pd0 = fmaf(acc[t][0], d0, fmaf(acc[t][1], d1, pd0));
            ps1 = fmaf(acc[t][2], s0, fmaf(acc[t][3], s1, ps1));
            pd1 = fmaf(acc[t][2], d0, fmaf(acc[t][3], d1, pd1));
        }
#pragma unroll
        for (int o = 1; o < 4; o <<= 1) {
            ps0 += __shfl_xor_sync(0xffffffffu, ps0, o);
            pd0 += __shfl_xor_sync(0xffffffffu, pd0, o);
            ps1 += __shfl_xor_sync(0xffffffffu, ps1, o);
            pd1 += __shfl_xor_sync(0xffffffffu, pd1, o);
        }
        const int Hh   = Nc >> 6;
        const int head = colBase >> 6;
        if (q == 0) {
            if (r0 < M) { as_out[r0 * Hh + head] = ps0; ad_out[r0 * Hh + head] = pd0; }
            if (r1 < M) { as_out[r1 * Hh + head] = ps1; ad_out[r1 * Hh + head] = pd1; }
        }
    }
}

// ---------------- aggregation layer 0: warp per dst, fp16 features, 1 LDG.128/edge ----------------
__global__ void __launch_bounds__(AGGW * 32)
k_agg0(const float* __restrict__ b0)
{
    const int d    = (blockIdx.x * blockDim.x + threadIdx.x) >> 5;
    const int lane = threadIdx.x & 31;
    const int wl   = threadIdx.x >> 5;
    if (d >= NN) return;

    __shared__ int   s_sm[AGGW][32];
    __shared__ float w_sm[AGGW][32 * 4];

    const int beg = g_row[d];
    const int n   = g_row[d + 1] - beg;
    const float4 ad = *(const float4*)(g_ad0 + d * 4);
    const int h     = lane >> 3;      // head of this lane's 8 channels
    const int choff = lane * 8;

    float4 accA = make_float4(0.f, 0.f, 0.f, 0.f);
    float4 accB = make_float4(0.f, 0.f, 0.f, 0.f);
    float  den  = 0.f;

    for (int base = 0; base < n; base += 32) {
        const int m = min(32, n - base);
        __syncwarp();
        if (lane < m) {
            int s = g_srcl[beg + base + lane];
            s_sm[wl][lane] = s;
            float4 a = *(const float4*)(g_as0 + s * 4);
            float4 w4;
            w4.x = __expf(leaky02(a.x + ad.x));
            w4.y = __expf(leaky02(a.y + ad.y));
            w4.z = __expf(leaky02(a.z + ad.z));
            w4.w = __expf(leaky02(a.w + ad.w));
            *(float4*)&w_sm[wl][lane * 4] = w4;
        }
        __syncwarp();

        const int P = 4;
        uint4 v[P];
#pragma unroll
        for (int j = 0; j < P; j++)
            if (j < m)
                v[j] = *(const uint4*)(g_lin0h + (size_t)s_sm[wl][j] * HC0 + choff);

        for (int i = 0; i < m; i++) {
            float w = w_sm[wl][i * 4 + h];
            uint4 pk = v[i & (P - 1)];
            int nx = i + P;
            if (nx < m)
                v[i & (P - 1)] = *(const uint4*)(g_lin0h + (size_t)s_sm[wl][nx] * HC0 + choff);
            den += w;
            float2 f0 = __half22float2(*(__half2*)&pk.x);
            float2 f1 = __half22float2(*(__half2*)&pk.y);
            float2 f2 = __half22float2(*(__half2*)&pk.z);
            float2 f3 = __half22float2(*(__half2*)&pk.w);
            accA.x = fmaf(w, f0.x, accA.x);
            accA.y = fmaf(w, f0.y, accA.y);
            accA.z = fmaf(w, f1.x, accA.z);
            accA.w = fmaf(w, f1.y, accA.w);
            accB.x = fmaf(w, f2.x, accB.x);
            accB.y = fmaf(w, f2.y, accB.y);
            accB.z = fmaf(w, f3.x, accB.z);
            accB.w = fmaf(w, f3.y, accB.w);
        }
    }

    const float inv = 1.f / (den + 1e-16f);
    float4 bbA = *(const float4*)(b0 + choff);
    float4 bbB = *(const float4*)(b0 + choff + 4);
    float4 oA, oB;
    oA.x = fmaxf(accA.x * inv + bbA.x, 0.f);
    oA.y = fmaxf(accA.y * inv + bbA.y, 0.f);
    oA.z = fmaxf(accA.z * inv + bbA.z, 0.f);
    oA.w = fmaxf(accA.w * inv + bbA.w, 0.f);
    oB.x = fmaxf(accB.x * inv + bbB.x, 0.f);
    oB.y = fmaxf(accB.y * inv + bbB.y, 0.f);
    oB.z = fmaxf(accB.z * inv + bbB.z, 0.f);
    oB.w = fmaxf(accB.w * inv + bbB.w, 0.f);
    float* op = g_feat + (size_t)d * HC0 + choff;
    *(float4*)(op)     = oA;
    *(float4*)(op + 4) = oB;
}

// ---------------- aggregation layer 1: warp per dst (fp32) ----------------
__global__ void __launch_bounds__(256)
k_agg1(const float* __restrict__ b1, float* __restrict__ out)
{
    const int d    = (blockIdx.x * blockDim.x + threadIdx.x) >> 5;
    const int lane = threadIdx.x & 31;
    if (d >= NN) return;

    const int beg = g_row[d];
    const int n   = g_row[d + 1] - beg;
    const float ad = g_ad1[d];

    float2 acc = make_float2(0.f, 0.f);
    float  den = 0.f;
    const int choff = lane * 2;

    for (int base = 0; base < n; base += 32) {
        const int m = min(32, n - base);
        int   s32 = 0;
        float w32 = 0.f;
        if (lane < m) {
            s32 = g_srcl[beg + base + lane];
            w32 = __expf(leaky02(g_as1[s32] + ad));
        }
        const int P = 4;
        float2 v[P];
#pragma unroll
        for (int j = 0; j < P; j++)
            if (j < m) {
                int s = __shfl_sync(0xffffffffu, s32, j);
                v[j] = *(const float2*)(g_lin1 + (size_t)s * HC1 + choff);
            }
        for (int i = 0; i < m; i++) {
            float  w  = __shfl_sync(0xffffffffu, w32, i);
            float2 vv = v[i & (P - 1)];
            int nx = i + P;
            if (nx < m) {
                int s = __shfl_sync(0xffffffffu, s32, nx);
                v[i & (P - 1)] = *(const float2*)(g_lin1 + (size_t)s * HC1 + choff);
            }
            den  += w;
            acc.x = fmaf(w, vv.x, acc.x);
            acc.y = fmaf(w, vv.y, acc.y);
        }
    }

    float inv = 1.f / (den + 1e-16f);
    float2 bb = *(const float2*)(b1 + choff);
    float2 o;
    o.x = acc.x * inv + bb.x;
    o.y = acc.y * inv + bb.y;
    *(float2*)(out + (size_t)d * HC1 + choff) = o;
}

// ---------------- launch ----------------
extern "C" void kernel_launch(void* const* d_in, const int* in_sizes, int n_in,
                              void* d_out, int out_size)
{
    const float* x      = (const float*)d_in[0];
    const int*   ei     = (const int*)  d_in[1];
    const float* W0     = (const float*)d_in[2];
    const float* att_s0 = (const float*)d_in[3];
    const float* att_d0 = (const float*)d_in[4];
    const float* b0     = (const float*)d_in[5];
    const float* W1     = (const float*)d_in[6];
    const float* att_s1 = (const float*)d_in[7];
    const float* att_d1 = (const float*)d_in[8];
    const float* b1     = (const float*)d_in[9];

    const int E    = in_sizes[1] / 2;
    const int Etot = E + NN;

    __half *p_lin0h;
    float  *p_feat, *p_lin1, *p_as0, *p_ad0, *p_as1, *p_ad1;
    cudaGetSymbolAddress((void**)&p_lin0h, g_lin0h);
    cudaGetSymbolAddress((void**)&p_feat,  g_feat);
    cudaGetSymbolAddress((void**)&p_lin1,  g_lin1);
    cudaGetSymbolAddress((void**)&p_as0,   g_as0);
    cudaGetSymbolAddress((void**)&p_ad0,   g_ad0);
    cudaGetSymbolAddress((void**)&p_as1,   g_as1);
    cudaGetSymbolAddress((void**)&p_ad1,   g_ad1);

    static cudaStream_t sB = nullptr;
    static cudaEvent_t  evFork = nullptr, evJoin = nullptr;
    if (sB == nullptr) {
        cudaStreamCreateWithFlags(&sB, cudaStreamNonBlocking);
        cudaEventCreateWithFlags(&evFork, cudaEventDisableTiming);
        cudaEventCreateWithFlags(&evJoin, cudaEventDisableTiming);
    }

    const int TB = 256;
    const int T4 = (Etot + 3) / 4;   // threads for 4-edge kernels

    // ---- fork: CSR build on side stream, concurrent with GEMM0 ----
    cudaEventRecord(evFork, 0);
    cudaStreamWaitEvent(sB, evFork, 0);
    k_zero_deg<<<(NN + TB - 1) / TB, TB, 0, sB>>>();
    k_hist<<<(T4 + TB - 1) / TB, TB, 0, sB>>>(ei, E, Etot, T4);
    k_scan<<<1, 1024, 0, sB>>>();
    k_scatter<<<(T4 + TB - 1) / TB, TB, 0, sB>>>(ei, E, Etot, T4);
    cudaEventRecord(evJoin, sB);

    // ---- layer 0 GEMM (tf32, fp16 out) ----
    {
        dim3 grid((NN + 127) / 128, HC0 / 64);
        gemm_tf32<__half><<<grid, 256>>>(x, W0, p_lin0h, NN, HC0, F0,
                                         att_s0, att_d0, p_as0, p_ad0);
    }

    cudaStreamWaitEvent(0, evJoin, 0);
    k_agg0<<<(NN * 32 + AGGW * 32 - 1) / (AGGW * 32), AGGW * 32>>>(b0);

    // ---- layer 1 (tf32, fp32 out) ----
    {
        dim3 grid((NN + 127) / 128, HC1 / 64);
        gemm_tf32<float><<<grid, 256>>>(p_feat, W1, p_lin1, NN, HC1, HC0,
                                        att_s1, att_d1, p_as1, p_ad1);
    }
    k_agg1<<<(NN * 32 + TB - 1) / TB, TB>>>(b1, (float*)d_out);
}

// round 10
// speedup vs baseline: 2.1383x; 1.4614x over previous
#include <cuda_runtime.h>
#include <cuda_fp16.h>
#include <cstdint>
#include <math.h>

// ---------------- problem constants ----------------
#define NN    50000
#define F0    128
#define H0    4
#define HC0   256
#define HC1   64
#define EMAX  900000
#define AGGW  8

// ---------------- scratch ----------------
__device__ __half g_lin0h[(size_t)NN * HC0];   // layer0 features, fp16
__device__ float  g_feat [(size_t)NN * HC0];   // relu(agg0+b0), fp32 (GEMM1 input)
__device__ __half g_lin1h[(size_t)NN * HC1];   // layer1 features, fp16
__device__ float  g_as0 [NN * H0];
__device__ float  g_ad0 [NN * H0];
__device__ float  g_as1 [NN];
__device__ float  g_ad1 [NN];
__device__ __align__(16) int g_deg [NN];
__device__ __align__(16) int g_row [NN + 4];
__device__ int    g_rank[EMAX];
__device__ int    g_srcl[EMAX];

__device__ __forceinline__ float leaky02(float v) { return v > 0.0f ? v : 0.2f * v; }

__device__ __forceinline__ unsigned tf32_of(float x) {
    unsigned u;
    asm("cvt.rna.tf32.f32 %0, %1;" : "=r"(u) : "f"(x));
    return u;
}

__device__ __forceinline__ void edge_sd(const int* __restrict__ ei, int e, int E, int& s, int& d) {
    if (e < E) { s = ei[e]; d = ei[E + e]; } else { s = e - E; d = e - E; }
}

__device__ __forceinline__ void store2(float* p, float a, float b) {
    *(float2*)p = make_float2(a, b);
}
__device__ __forceinline__ void store2(__half* p, float a, float b) {
    *(__half2*)p = __floats2half2_rn(a, b);
}

// ---------------- CSR build (atomic-free placement) ----------------
__global__ void k_zero_deg() {
    int i = blockIdx.x * blockDim.x + threadIdx.x;
    if (i < NN) g_deg[i] = 0;
}
// histogram + per-edge rank (atomic return value)
__global__ void k_hist(const int* __restrict__ ei, int E, int Etot, int T) {
    int t = blockIdx.x * blockDim.x + threadIdx.x;
    if (t >= T) return;
#pragma unroll
    for (int i = 0; i < 4; i++) {
        int e = t + i * T;
        if (e < Etot) {
            int s, d; edge_sd(ei, e, E, s, d);
            g_rank[e] = atomicAdd(&g_deg[d], 1);
        }
    }
}
// single-block exclusive scan, int4-vectorized (NN % 4 == 0)
__global__ void k_scan() {
    __shared__ int ssum[1024];
    const int t  = threadIdx.x;
    const int CH = 52;                 // 13 int4 per thread; 962 threads cover NN
    const int beg = t * CH;
    int s = 0;
    if (beg < NN) {
#pragma unroll
        for (int j = 0; j < 13; j++) {
            int idx = beg + j * 4;
            if (idx < NN) {
                int4 v = *(const int4*)(g_deg + idx);
                s += v.x + v.y + v.z + v.w;
            }
        }
    }
    ssum[t] = s;
    __syncthreads();
    for (int o = 1; o < 1024; o <<= 1) {
        int v = (t >= o) ? ssum[t - o] : 0;
        __syncthreads();
        ssum[t] += v;
        __syncthreads();
    }
    int run = (t == 0) ? 0 : ssum[t - 1];
    if (beg < NN) {
#pragma unroll
        for (int j = 0; j < 13; j++) {
            int idx = beg + j * 4;
            if (idx < NN) {
                int4 v = *(const int4*)(g_deg + idx);
                int4 r;
                r.x = run; run += v.x;
                r.y = run; run += v.y;
                r.z = run; run += v.z;
                r.w = run; run += v.w;
                *(int4*)(g_row + idx) = r;
            }
        }
    }
    if (t == 0) g_row[NN] = ssum[1023];
}
// placement: no atomics
__global__ void k_place(const int* __restrict__ ei, int E, int Etot, int T) {
    int t = blockIdx.x * blockDim.x + threadIdx.x;
    if (t >= T) return;
#pragma unroll
    for (int i = 0; i < 4; i++) {
        int e = t + i * T;
        if (e < Etot) {
            int s, d; edge_sd(ei, e, E, s, d);
            g_srcl[g_row[d] + g_rank[e]] = s;
        }
    }
}

// ---------------- tf32 tensor-core GEMM + fused attention-coef epilogue ----------------
#define TBK 32
template<typename TO>
__global__ void __launch_bounds__(256)
gemm_tf32(const float* __restrict__ A, const float* __restrict__ B,
          TO* __restrict__ C, int M, int Nc, int K,
          const float* __restrict__ att_s, const float* __restrict__ att_d,
          float* __restrict__ as_out, float* __restrict__ ad_out)
{
    __shared__ unsigned As[128][TBK + 4];
    __shared__ unsigned Bs[64][TBK + 4];

    const int tid  = threadIdx.x;
    const int lane = tid & 31;
    const int warp = tid >> 5;
    const int g    = lane >> 2;
    const int q    = lane & 3;
    const int rowBase = blockIdx.x * 128;
    const int colBase = blockIdx.y * 64;
    const int warpRow = warp * 16;

    float acc[8][4];
#pragma unroll
    for (int t = 0; t < 8; t++)
#pragma unroll
        for (int j = 0; j < 4; j++) acc[t][j] = 0.f;

    for (int k0 = 0; k0 < K; k0 += TBK) {
#pragma unroll
        for (int i = 0; i < 4; i++) {
            int f  = tid + i * 256;
            int r  = f >> 3;
            int c4 = (f & 7) * 4;
            float4 v = make_float4(0.f, 0.f, 0.f, 0.f);
            int gr = rowBase + r;
            if (gr < M) v = *(const float4*)(A + (size_t)gr * K + k0 + c4);
            As[r][c4+0] = tf32_of(v.x); As[r][c4+1] = tf32_of(v.y);
            As[r][c4+2] = tf32_of(v.z); As[r][c4+3] = tf32_of(v.w);
        }
#pragma unroll
        for (int i = 0; i < 2; i++) {
            int f  = tid + i * 256;
            int r  = f >> 3;
            int c4 = (f & 7) * 4;
            float4 v = *(const float4*)(B + (size_t)(colBase + r) * K + k0 + c4);
            Bs[r][c4+0] = tf32_of(v.x); Bs[r][c4+1] = tf32_of(v.y);
            Bs[r][c4+2] = tf32_of(v.z); Bs[r][c4+3] = tf32_of(v.w);
        }
        __syncthreads();

#pragma unroll
        for (int kk = 0; kk < TBK; kk += 8) {
            unsigned a0 = As[warpRow + g    ][kk + q];
            unsigned a1 = As[warpRow + g + 8][kk + q];
            unsigned a2 = As[warpRow + g    ][kk + q + 4];
            unsigned a3 = As[warpRow + g + 8][kk + q + 4];
#pragma unroll
            for (int t = 0; t < 8; t++) {
                unsigned b0 = Bs[t * 8 + g][kk + q];
                unsigned b1 = Bs[t * 8 + g][kk + q + 4];
                asm("mma.sync.aligned.m16n8k8.row.col.f32.tf32.tf32.f32 "
                    "{%0,%1,%2,%3}, {%4,%5,%6,%7}, {%8,%9}, {%0,%1,%2,%3};"
                    : "+f"(acc[t][0]), "+f"(acc[t][1]), "+f"(acc[t][2]), "+f"(acc[t][3])
                    : "r"(a0), "r"(a1), "r"(a2), "r"(a3), "r"(b0), "r"(b1));
            }
        }
        __syncthreads();
    }

    const int r0 = rowBase + warpRow + g;
    const int r1 = r0 + 8;
#pragma unroll
    for (int t = 0; t < 8; t++) {
        int col = colBase + t * 8 + q * 2;
        if (r0 < M) store2(C + (size_t)r0 * Nc + col, acc[t][0], acc[t][1]);
        if (r1 < M) store2(C + (size_t)r1 * Nc + col, acc[t][2], acc[t][3]);
    }

    {
        float ps0 = 0.f, pd0 = 0.f, ps1 = 0.f, pd1 = 0.f;
#pragma unroll
        for (int t = 0; t < 8; t++) {
            int col = colBase + t * 8 + q * 2;
            float s0 = att_s[col], s1 = att_s[col + 1];
            float d0 = att_d[col], d1 = att_d[col + 1];
            ps0 = fmaf(acc[t][0], s0, fmaf(acc[t][1], s1, ps0));
            pd0 = fmaf(acc[t][0], d0, fmaf(acc[t][1], d1, pd0));
            ps1 = fmaf(acc[t][2], s0, fmaf(acc[t][3], s1, ps1));
            pd1 = fmaf(acc[t][2], d0, fmaf(acc[t][3], d1, pd1));
        }
#pragma unroll
        for (int o = 1; o < 4; o <<= 1) {
            ps0 += __shfl_xor_sync(0xffffffffu, ps0, o);
            pd0 += __shfl_xor_sync(0xffffffffu, pd0, o);
            ps1 += __shfl_xor_sync(0xffffffffu, ps1, o);
            pd1 += __shfl_xor_sync(0xffffffffu, pd1, o);
        }
        const int Hh   = Nc >> 6;
        const int head = colBase >> 6;
        if (q == 0) {
            if (r0 < M) { as_out[r0 * Hh + head] = ps0; ad_out[r0 * Hh + head] = pd0; }
            if (r1 < M) { as_out[r1 * Hh + head] = ps1; ad_out[r1 * Hh + head] = pd1; }
        }
    }
}

// ---------------- aggregation layer 0: warp per dst, fp16 features ----------------
__global__ void __launch_bounds__(AGGW * 32)
k_agg0(const float* __restrict__ b0)
{
    const int d    = (blockIdx.x * blockDim.x + threadIdx.x) >> 5;
    const int lane = threadIdx.x & 31;
    const int wl   = threadIdx.x >> 5;
    if (d >= NN) return;

    __shared__ int   s_sm[AGGW][32];
    __shared__ float w_sm[AGGW][32 * 4];

    const int beg = g_row[d];
    const int n   = g_row[d + 1] - beg;
    const float4 ad = *(const float4*)(g_ad0 + d * 4);
    const int h     = lane >> 3;
    const int choff = lane * 8;

    float4 accA = make_float4(0.f, 0.f, 0.f, 0.f);
    float4 accB = make_float4(0.f, 0.f, 0.f, 0.f);
    float  den  = 0.f;

    for (int base = 0; base < n; base += 32) {
        const int m = min(32, n - base);
        __syncwarp();
        if (lane < m) {
            int s = g_srcl[beg + base + lane];
            s_sm[wl][lane] = s;
            float4 a = *(const float4*)(g_as0 + s * 4);
            float4 w4;
            w4.x = __expf(leaky02(a.x + ad.x));
            w4.y = __expf(leaky02(a.y + ad.y));
            w4.z = __expf(leaky02(a.z + ad.z));
            w4.w = __expf(leaky02(a.w + ad.w));
            *(float4*)&w_sm[wl][lane * 4] = w4;
        }
        __syncwarp();

        const int P = 4;
        uint4 v[P];
#pragma unroll
        for (int j = 0; j < P; j++)
            if (j < m)
                v[j] = *(const uint4*)(g_lin0h + (size_t)s_sm[wl][j] * HC0 + choff);

        for (int i = 0; i < m; i++) {
            float w = w_sm[wl][i * 4 + h];
            uint4 pk = v[i & (P - 1)];
            int nx = i + P;
            if (nx < m)
                v[i & (P - 1)] = *(const uint4*)(g_lin0h + (size_t)s_sm[wl][nx] * HC0 + choff);
            den += w;
            float2 f0 = __half22float2(*(__half2*)&pk.x);
            float2 f1 = __half22float2(*(__half2*)&pk.y);
            float2 f2 = __half22float2(*(__half2*)&pk.z);
            float2 f3 = __half22float2(*(__half2*)&pk.w);
            accA.x = fmaf(w, f0.x, accA.x);
            accA.y = fmaf(w, f0.y, accA.y);
            accA.z = fmaf(w, f1.x, accA.z);
            accA.w = fmaf(w, f1.y, accA.w);
            accB.x = fmaf(w, f2.x, accB.x);
            accB.y = fmaf(w, f2.y, accB.y);
            accB.z = fmaf(w, f3.x, accB.z);
            accB.w = fmaf(w, f3.y, accB.w);
        }
    }

    const float inv = 1.f / (den + 1e-16f);
    float4 bbA = *(const float4*)(b0 + choff);
    float4 bbB = *(const float4*)(b0 + choff + 4);
    float4 oA, oB;
    oA.x = fmaxf(accA.x * inv + bbA.x, 0.f);
    oA.y = fmaxf(accA.y * inv + bbA.y, 0.f);
    oA.z = fmaxf(accA.z * inv + bbA.z, 0.f);
    oA.w = fmaxf(accA.w * inv + bbA.w, 0.f);
    oB.x = fmaxf(accB.x * inv + bbB.x, 0.f);
    oB.y = fmaxf(accB.y * inv + bbB.y, 0.f);
    oB.z = fmaxf(accB.z * inv + bbB.z, 0.f);
    oB.w = fmaxf(accB.w * inv + bbB.w, 0.f);
    float* op = g_feat + (size_t)d * HC0 + choff;
    *(float4*)(op)     = oA;
    *(float4*)(op + 4) = oB;
}

// ---------------- aggregation layer 1: half-warp per dst, fp16 features ----------------
__global__ void __launch_bounds__(256)
k_agg1(const float* __restrict__ b1, float* __restrict__ out)
{
    const int d    = (blockIdx.x * blockDim.x + threadIdx.x) >> 4;  // half-warp per dst
    const int l    = threadIdx.x & 15;
    const int hwb  = threadIdx.x >> 4;              // half-warp index in block (0..15)
    const int hwl  = (threadIdx.x >> 4) & 1;        // which half of the warp
    const unsigned mask = 0xFFFFu << (hwl * 16);
    if (d >= NN) return;

    __shared__ int   s_sm[16][16];
    __shared__ float w_sm[16][16];

    const int beg = g_row[d];
    const int n   = g_row[d + 1] - beg;
    const float ad = g_ad1[d];
    const int choff = l * 4;                        // 4 channels per lane

    float4 acc = make_float4(0.f, 0.f, 0.f, 0.f);
    float  den = 0.f;

    for (int base = 0; base < n; base += 16) {
        const int m = min(16, n - base);
        __syncwarp(mask);
        if (l < m) {
            int s = g_srcl[beg + base + l];
            s_sm[hwb][l] = s;
            w_sm[hwb][l] = __expf(leaky02(g_as1[s] + ad));
        }
        __syncwarp(mask);

        const int P = 4;
        uint2 v[P];
#pragma unroll
        for (int j = 0; j < P; j++)
            if (j < m)
                v[j] = *(const uint2*)(g_lin1h + (size_t)s_sm[hwb][j] * HC1 + choff);

        for (int i = 0; i < m; i++) {
            float w  = w_sm[hwb][i];
            uint2 pk = v[i & (P - 1)];
            int nx = i + P;
            if (nx < m)
                v[i & (P - 1)] = *(const uint2*)(g_lin1h + (size_t)s_sm[hwb][nx] * HC1 + choff);
            den += w;
            float2 f0 = __half22float2(*(__half2*)&pk.x);
            float2 f1 = __half22float2(*(__half2*)&pk.y);
            acc.x = fmaf(w, f0.x, acc.x);
            acc.y = fmaf(w, f0.y, acc.y);
            acc.z = fmaf(w, f1.x, acc.z);
            acc.w = fmaf(w, f1.y, acc.w);
        }
    }

    const float inv = 1.f / (den + 1e-16f);
    float4 bb = *(const float4*)(b1 + choff);
    float4 o;
    o.x = acc.x * inv + bb.x;
    o.y = acc.y * inv + bb.y;
    o.z = acc.z * inv + bb.z;
    o.w = acc.w * inv + bb.w;
    *(float4*)(out + (size_t)d * HC1 + choff) = o;
}

// ---------------- launch ----------------
extern "C" void kernel_launch(void* const* d_in, const int* in_sizes, int n_in,
                              void* d_out, int out_size)
{
    const float* x      = (const float*)d_in[0];
    const int*   ei     = (const int*)  d_in[1];
    const float* W0     = (const float*)d_in[2];
    const float* att_s0 = (const float*)d_in[3];
    const float* att_d0 = (const float*)d_in[4];
    const float* b0     = (const float*)d_in[5];
    const float* W1     = (const float*)d_in[6];
    const float* att_s1 = (const float*)d_in[7];
    const float* att_d1 = (const float*)d_in[8];
    const float* b1     = (const float*)d_in[9];

    const int E    = in_sizes[1] / 2;
    const int Etot = E + NN;

    __half *p_lin0h, *p_lin1h;
    float  *p_feat, *p_as0, *p_ad0, *p_as1, *p_ad1;
    cudaGetSymbolAddress((void**)&p_lin0h, g_lin0h);
    cudaGetSymbolAddress((void**)&p_lin1h, g_lin1h);
    cudaGetSymbolAddress((void**)&p_feat,  g_feat);
    cudaGetSymbolAddress((void**)&p_as0,   g_as0);
    cudaGetSymbolAddress((void**)&p_ad0,   g_ad0);
    cudaGetSymbolAddress((void**)&p_as1,   g_as1);
    cudaGetSymbolAddress((void**)&p_ad1,   g_ad1);

    static cudaStream_t sB = nullptr;
    static cudaEvent_t  evFork = nullptr, evJoin = nullptr;
    if (sB == nullptr) {
        cudaStreamCreateWithFlags(&sB, cudaStreamNonBlocking);
        cudaEventCreateWithFlags(&evFork, cudaEventDisableTiming);
        cudaEventCreateWithFlags(&evJoin, cudaEventDisableTiming);
    }

    const int TB = 256;
    const int T4 = (Etot + 3) / 4;

    // ---- fork: CSR build on side stream, concurrent with GEMM0 ----
    cudaEventRecord(evFork, 0);
    cudaStreamWaitEvent(sB, evFork, 0);
    k_zero_deg<<<(NN + TB - 1) / TB, TB, 0, sB>>>();
    k_hist<<<(T4 + TB - 1) / TB, TB, 0, sB>>>(ei, E, Etot, T4);
    k_scan<<<1, 1024, 0, sB>>>();
    k_place<<<(T4 + TB - 1) / TB, TB, 0, sB>>>(ei, E, Etot, T4);
    cudaEventRecord(evJoin, sB);

    // ---- layer 0 GEMM (tf32, fp16 out) ----
    {
        dim3 grid((NN + 127) / 128, HC0 / 64);
        gemm_tf32<__half><<<grid, 256>>>(x, W0, p_lin0h, NN, HC0, F0,
                                         att_s0, att_d0, p_as0, p_ad0);
    }

    cudaStreamWaitEvent(0, evJoin, 0);
    k_agg0<<<(NN * 32 + AGGW * 32 - 1) / (AGGW * 32), AGGW * 32>>>(b0);

    // ---- layer 1 (tf32, fp16 out) ----
    {
        dim3 grid((NN + 127) / 128, HC1 / 64);
        gemm_tf32<__half><<<grid, 256>>>(p_feat, W1, p_lin1h, NN, HC1, HC0,
                                         att_s1, att_d1, p_as1, p_ad1);
    }
    k_agg1<<<(NN * 16 + TB - 1) / TB, TB>>>(b1, (float*)d_out);
}